// round 16
// baseline (speedup 1.0000x reference)
#include <cuda_runtime.h>
#include <math.h>
#include <stdint.h>

#define B_  8
#define T_  2048
#define C_  1024
#define NF_ 64
#define M_  (B_*T_)      /* 16384 */
#define TNF 128

// ---------------- scratch (device globals) ----------------
__device__ float    g_q[(size_t)M_ * C_];      // final q only (tf32)
__device__ float    g_v[(size_t)M_ * C_];      // fp32
__device__ float    g_A[(size_t)M_ * C_];      // x_tf32, later (q*v*s)_tf32
__device__ float    g_G[(size_t)M_ * TNF];     // fp32, loop state
__device__ float    g_SC[(size_t)M_ * TNF];    // tf32
__device__ float    g_Wcat[C_ * TNF];          // fp32 exact [Wtop|Wbot]
__device__ float    g_Wb1[C_ * 1152];          // tf32 [attn_W_v | Wq@Wcat]
__device__ float    g_Wb2[TNF * 1152];         // tf32 [out_W | out_W@Wcat]
__device__ float    g_projW[C_ * C_];          // tf32
__device__ float    g_bias1[1152];             // [attn_b_v | attn_b_q@Wcat]
__device__ float    g_bias2[1152];             // [out_b | out_b@Wcat]
__device__ float    g_idG[NF_];
__device__ unsigned g_rm[2][M_];

enum { MODE_SPLIT = 0, MODE_LOOP = 1, MODE_SCAN = 2, MODE_PROJ = 3 };

__device__ __forceinline__ uint32_t f2tf(float f) {
    uint32_t u; asm("cvt.rna.tf32.f32 %0, %1;" : "=r"(u) : "f"(f)); return u;
}
__device__ __forceinline__ float f2tff(float f) { return __uint_as_float(f2tf(f)); }
__device__ __forceinline__ void mma8(float* c, const uint32_t* a, const uint32_t* b) {
    asm volatile(
        "mma.sync.aligned.m16n8k8.row.col.f32.tf32.tf32.f32 "
        "{%0,%1,%2,%3},{%4,%5,%6,%7},{%8,%9},{%0,%1,%2,%3};\n"
        : "+f"(c[0]), "+f"(c[1]), "+f"(c[2]), "+f"(c[3])
        : "r"(a[0]), "r"(a[1]), "r"(a[2]), "r"(a[3]), "r"(b[0]), "r"(b[1]));
}
__device__ __forceinline__ void cpa16(uint32_t dst, const void* src) {
    asm volatile("cp.async.cg.shared.global [%0], [%1], 16;\n" :: "r"(dst), "l"(src));
}

// ---------------- pipelined tf32 tensor-core GEMM (BM=128, BN=128, BK=32) ----------------
template<int MODE>
__global__ __launch_bounds__(256, 2)
void gemm_tc(const float* __restrict__ A, const float* __restrict__ Bm,
             const float* __restrict__ bias, float* __restrict__ Cmat,
             unsigned* __restrict__ rmw, int N, int ldb, int K)
{
    constexpr int BM = 128, WM = 32, WN = 64, BK = 32;
    constexpr int WARPS_N = 2;
    constexpr int MT = WM / 16, NT = WN / 8;
    constexpr int ASZ = BM * 36;
    constexpr int BSZ = BK * 128;

    extern __shared__ float sm[];
    const uint32_t smbase = (uint32_t)__cvta_generic_to_shared(sm);

    const int tid  = threadIdx.x;
    const int bm   = blockIdx.y * BM;
    const int bn   = blockIdx.x * 128;
    const int warp = tid >> 5, lane = tid & 31;
    const int grp  = lane >> 2, tig = lane & 3;
    const int wm   = warp / WARPS_N, wn = warp % WARPS_N;

    float acc[MT][NT][4];
#pragma unroll
    for (int i = 0; i < MT; i++)
#pragma unroll
        for (int j = 0; j < NT; j++)
#pragma unroll
            for (int r = 0; r < 4; r++) acc[i][j][r] = 0.f;

    const int lr = tid >> 3, lc = (tid & 7) * 4;
    const int kr = tid >> 5;
    const int kchunk = tid & 31;
    const int kphys  = (kchunk ^ ((kr & 3) << 1)) * 4;

    auto ldA = [&](int st, int k0) {
#pragma unroll
        for (int i = 0; i < BM / 32; i++) {
            uint32_t d = smbase + (uint32_t)(st * ASZ + (lr + 32 * i) * 36 + lc) * 4u;
            cpa16(d, &A[(size_t)(bm + lr + 32 * i) * K + k0 + lc]);
        }
    };
    auto ldB = [&](int st, int k0) {
#pragma unroll
        for (int i = 0; i < 4; i++) {
            uint32_t d = smbase + (uint32_t)(2 * ASZ + st * BSZ + (kr + 8 * i) * 128 + kphys) * 4u;
            cpa16(d, &Bm[(size_t)(k0 + kr + 8 * i) * ldb + bn + kchunk * 4]);
        }
    };

    ldA(0, 0); ldB(0, 0);
    asm volatile("cp.async.commit_group;\n");

    const int nk = K / BK;
    for (int it = 0; it < nk; it++) {
        const int st = it & 1;
        if (it + 1 < nk) {
            ldA(st ^ 1, (it + 1) * BK);
            ldB(st ^ 1, (it + 1) * BK);
            asm volatile("cp.async.commit_group;\n");
            asm volatile("cp.async.wait_group 1;\n");
        } else {
            asm volatile("cp.async.wait_group 0;\n");
        }
        __syncthreads();

        const uint32_t* As32 = (const uint32_t*)sm + st * ASZ;
        const uint32_t* Bs32 = (const uint32_t*)sm + 2 * ASZ + st * BSZ;

#pragma unroll
        for (int ks = 0; ks < 4; ks++) {
            const int kk = ks * 8;
            uint32_t af[MT][4], bf[NT][2];
#pragma unroll
            for (int mt = 0; mt < MT; mt++) {
                int r = wm * WM + mt * 16 + grp;
                af[mt][0] = As32[r * 36 + kk + tig];
                af[mt][1] = As32[(r + 8) * 36 + kk + tig];
                af[mt][2] = As32[r * 36 + kk + tig + 4];
                af[mt][3] = As32[(r + 8) * 36 + kk + tig + 4];
            }
#pragma unroll
            for (int nt = 0; nt < NT; nt++) {
                int c = wn * WN + nt * 8 + grp;
                int p = (((c >> 2) ^ (tig << 1)) << 2) | (c & 3);
                bf[nt][0] = Bs32[(kk + tig) * 128 + p];
                bf[nt][1] = Bs32[(kk + tig + 4) * 128 + p];
            }
#pragma unroll
            for (int mt = 0; mt < MT; mt++)
#pragma unroll
                for (int nt = 0; nt < NT; nt++)
                    mma8(acc[mt][nt], af[mt], bf[nt]);
        }
        __syncthreads();
    }

    // ---------------- epilogue ----------------
#pragma unroll
    for (int mt = 0; mt < MT; mt++) {
        int row0 = bm + wm * WM + mt * 16 + grp;
        float mx0 = 0.f, mx1 = 0.f;
#pragma unroll
        for (int nt = 0; nt < NT; nt++) {
            int col = bn + wn * WN + nt * 8 + tig * 2;
            float b0 = bias[col], b1 = bias[col + 1];
            float v0 = acc[mt][nt][0] + b0, v1 = acc[mt][nt][1] + b1;
            float v2 = acc[mt][nt][2] + b0, v3 = acc[mt][nt][3] + b1;
            if (MODE == MODE_SPLIT) {
                if (col < C_) {
                    *(float2*)&g_v[(size_t)row0 * C_ + col]       = make_float2(v0, v1);
                    *(float2*)&g_v[(size_t)(row0 + 8) * C_ + col] = make_float2(v2, v3);
                } else {
                    int lcol = col - C_;
                    *(float2*)&g_G[(size_t)row0 * TNF + lcol]       = make_float2(v0, v1);
                    *(float2*)&g_G[(size_t)(row0 + 8) * TNF + lcol] = make_float2(v2, v3);
                }
            } else if (MODE == MODE_LOOP) {
                if (col < C_) {
                    mx0 = fmaxf(mx0, fmaxf(fabsf(v0), fabsf(v1)));
                    mx1 = fmaxf(mx1, fmaxf(fabsf(v2), fabsf(v3)));
                } else {
                    int lcol = col - C_;
                    *(float2*)&g_G[(size_t)row0 * TNF + lcol]       = make_float2(v0, v1);
                    *(float2*)&g_G[(size_t)(row0 + 8) * TNF + lcol] = make_float2(v2, v3);
                }
            } else if (MODE == MODE_SCAN) {
                mx0 = fmaxf(mx0, fmaxf(fabsf(v0), fabsf(v1)));
                mx1 = fmaxf(mx1, fmaxf(fabsf(v2), fabsf(v3)));
                *(float2*)&g_q[(size_t)row0 * C_ + col]       = make_float2(f2tff(v0), f2tff(v1));
                *(float2*)&g_q[(size_t)(row0 + 8) * C_ + col] = make_float2(f2tff(v2), f2tff(v3));
            } else {
                *(float2*)&Cmat[(size_t)row0 * N + col]       = make_float2(v0, v1);
                *(float2*)&Cmat[(size_t)(row0 + 8) * N + col] = make_float2(v2, v3);
            }
        }
        if (MODE == MODE_SCAN || (MODE == MODE_LOOP && bn < C_)) {
#pragma unroll
            for (int off = 1; off < 4; off <<= 1) {
                mx0 = fmaxf(mx0, __shfl_xor_sync(0xffffffffu, mx0, off));
                mx1 = fmaxf(mx1, __shfl_xor_sync(0xffffffffu, mx1, off));
            }
            if (tig == 0) {
                atomicMax(&rmw[row0],     __float_as_uint(mx0));
                atomicMax(&rmw[row0 + 8], __float_as_uint(mx1));
            }
        }
    }
}

// ---------------- pre-pass kernels ----------------
__global__ void cvt_k(const float* __restrict__ src, float* __restrict__ dst)
{
    size_t i = ((size_t)blockIdx.x * 256 + threadIdx.x) * 4;
    float4 v = *(const float4*)&src[i];
    v.x = f2tff(v.x); v.y = f2tff(v.y); v.z = f2tff(v.z); v.w = f2tff(v.w);
    *(float4*)&dst[i] = v;
}

__global__ void pack_wcat_k(const float* __restrict__ freqW)
{
    int idx = blockIdx.x * 256 + threadIdx.x;      // < 1024*128
    int k = idx >> 7, j = idx & 127;
    g_Wcat[idx] = (j < 64) ? freqW[k * 64 + j] : freqW[(k + 1024) * 64 + (j - 64)];
}

__global__ void wb1_k(const float* __restrict__ attnW)
{
    int i = blockIdx.y * 2 + (threadIdx.x >> 7);
    int c = blockIdx.x * 128 + (threadIdx.x & 127);
    float w;
    if (c < C_) {
        w = attnW[(size_t)i * 2048 + C_ + c];               // v-columns
    } else {
        int j = c - C_;                                     // W1 = Wq @ Wcat
        float s = 0.f;
        for (int k = 0; k < C_; k++)
            s = fmaf(attnW[(size_t)i * 2048 + k], g_Wcat[k * TNF + j], s);
        w = s;
    }
    g_Wb1[i * 1152 + c] = f2tff(w);
}

__global__ void wb2_k(const float* __restrict__ outW)
{
    int i = blockIdx.y * 2 + (threadIdx.x >> 7);
    int c = blockIdx.x * 128 + (threadIdx.x & 127);
    float w;
    if (c < C_) {
        w = outW[(size_t)i * C_ + c];
    } else {
        int j = c - C_;                                     // W2 = out_W @ Wcat
        float s = 0.f;
        for (int k = 0; k < C_; k++)
            s = fmaf(outW[(size_t)i * C_ + k], g_Wcat[k * TNF + j], s);
        w = s;
    }
    g_Wb2[i * 1152 + c] = f2tff(w);
}

__global__ void bias1_k(const float* __restrict__ attn_b)
{
    int c = blockIdx.x * 256 + threadIdx.x;
    if (c >= 1152) return;
    if (c < C_) { g_bias1[c] = attn_b[C_ + c]; return; }
    int j = c - C_;
    float s = 0.f;
    for (int k = 0; k < C_; k++) s = fmaf(attn_b[k], g_Wcat[k * TNF + j], s);
    g_bias1[c] = s;
}

__global__ void bias2_k(const float* __restrict__ out_b)
{
    int c = blockIdx.x * 256 + threadIdx.x;
    if (c >= 1152) return;
    if (c < C_) { g_bias2[c] = out_b[c]; return; }
    int j = c - C_;
    float s = 0.f;
    for (int k = 0; k < C_; k++) s = fmaf(out_b[k], g_Wcat[k * TNF + j], s);
    g_bias2[c] = s;
}

__global__ void idg_k(const float* __restrict__ freqW, const float* __restrict__ identity)
{
    int j = threadIdx.x;   // 64
    float s = 0.f;
    for (int k = 0; k < C_; k++) s = fmaf(identity[k], freqW[k * 64 + j], s);
    g_idG[j] = s;
}

__global__ void init_rm_k()
{
    g_rm[0][blockIdx.x * 256 + threadIdx.x] = __float_as_uint(1.0f - 1e-6f);
}

// shift + scale + sincos -> g_SC (tf32); zero rmnext. 4 j's per thread.
__global__ __launch_bounds__(256)
void sc_k(const float* __restrict__ freq_b, int n,
          const unsigned* __restrict__ rmprev, unsigned* __restrict__ rmnext)
{
    int idx = blockIdx.x * 256 + threadIdx.x;      // < M*16
    int row = idx >> 4, jq = (idx & 15) * 4;
    if (jq == 0) rmnext[row] = 0u;
    int t = row & (T_ - 1);
    float sown = 1.f / (__uint_as_float(rmprev[row]) + 1e-6f);
    float4 g2 = *(const float4*)&g_G[(size_t)row * TNF + 64 + jq];
    float4 g1;
    if (t >= n) {
        float sp = 1.f / (__uint_as_float(rmprev[row - n]) + 1e-6f);
        g1 = *(const float4*)&g_G[(size_t)(row - n) * TNF + jq];
        g1.x *= sp; g1.y *= sp; g1.z *= sp; g1.w *= sp;
    } else {
        g1 = *(const float4*)&g_idG[jq];
    }
    float4 fb = *(const float4*)&freq_b[jq];
    float f0 = g1.x + g2.x * sown + fb.x;
    float f1 = g1.y + g2.y * sown + fb.y;
    float f2 = g1.z + g2.z * sown + fb.z;
    float f3 = g1.w + g2.w * sown + fb.w;
    float s0, c0, s1, c1, s2, c2, s3, c3;
    sincosf(f0, &s0, &c0); sincosf(f1, &s1, &c1);
    sincosf(f2, &s2, &c2); sincosf(f3, &s3, &c3);
    *(float4*)&g_SC[(size_t)row * TNF + jq] =
        make_float4(f2tff(s0), f2tff(s1), f2tff(s2), f2tff(s3));
    *(float4*)&g_SC[(size_t)row * TNF + 64 + jq] =
        make_float4(f2tff(c0), f2tff(c1), f2tff(c2), f2tff(c3));
}

// A_proj = tf32(q * v * s)
__global__ __launch_bounds__(256)
void aproj_k(const unsigned* __restrict__ rm)
{
    size_t i = ((size_t)blockIdx.x * 256 + threadIdx.x) * 4;
    int row = (int)(i >> 10);
    float s = 1.f / (__uint_as_float(rm[row]) + 1e-6f);
    float4 q = *(const float4*)&g_q[i];
    float4 v = *(const float4*)&g_v[i];
    q.x = f2tff(q.x * v.x * s); q.y = f2tff(q.y * v.y * s);
    q.z = f2tff(q.z * v.z * s); q.w = f2tff(q.w * v.w * s);
    *(float4*)&g_A[i] = q;
}

// ---------------- launch ----------------
extern "C" void kernel_launch(void* const* d_in, const int* in_sizes, int n_in,
                              void* d_out, int out_size)
{
    (void)in_sizes; (void)n_in; (void)out_size;
    const float* x        = (const float*)d_in[0];
    const float* attn_W   = (const float*)d_in[1];
    const float* attn_b   = (const float*)d_in[2];
    const float* freq_W   = (const float*)d_in[3];
    const float* freq_b   = (const float*)d_in[4];
    const float* out_W    = (const float*)d_in[5];
    const float* out_b    = (const float*)d_in[6];
    const float* proj_W   = (const float*)d_in[7];
    const float* proj_b   = (const float*)d_in[8];
    const float* identity = (const float*)d_in[9];
    float* out = (float*)d_out;

    float *Ap, *SCp, *Wb1p, *Wb2p, *pWp, *b1p, *b2p;
    unsigned* rmp;
    cudaGetSymbolAddress((void**)&Ap,   g_A);
    cudaGetSymbolAddress((void**)&SCp,  g_SC);
    cudaGetSymbolAddress((void**)&Wb1p, g_Wb1);
    cudaGetSymbolAddress((void**)&Wb2p, g_Wb2);
    cudaGetSymbolAddress((void**)&pWp,  g_projW);
    cudaGetSymbolAddress((void**)&b1p,  g_bias1);
    cudaGetSymbolAddress((void**)&b2p,  g_bias2);
    cudaGetSymbolAddress((void**)&rmp,  g_rm);

    constexpr int SMEM = 2 * (128 * 36 + 32 * 128) * 4;   // 69632
    cudaFuncSetAttribute(gemm_tc<MODE_SPLIT>, cudaFuncAttributeMaxDynamicSharedMemorySize, SMEM);
    cudaFuncSetAttribute(gemm_tc<MODE_LOOP>,  cudaFuncAttributeMaxDynamicSharedMemorySize, SMEM);
    cudaFuncSetAttribute(gemm_tc<MODE_SCAN>,  cudaFuncAttributeMaxDynamicSharedMemorySize, SMEM);
    cudaFuncSetAttribute(gemm_tc<MODE_PROJ>,  cudaFuncAttributeMaxDynamicSharedMemorySize, SMEM);

    // pre-pass
    pack_wcat_k<<<512, 256>>>(freq_W);
    cvt_k<<<(M_ * C_) / 1024, 256>>>(x, Ap);
    cvt_k<<<(C_ * C_) / 1024, 256>>>(proj_W, pWp);
    wb1_k<<<dim3(9, 512), 256>>>(attn_W);
    wb2_k<<<dim3(9, 64), 256>>>(out_W);
    bias1_k<<<5, 256>>>(attn_b);
    bias2_k<<<5, 256>>>(out_b);
    idg_k<<<1, 64>>>(freq_W, identity);
    init_rm_k<<<M_ / 256, 256>>>();

    // split: [v | G0] = x @ [Wv | Wq@Wcat] + bias1
    gemm_tc<MODE_SPLIT>
        <<<dim3(9, M_ / 128), 256, SMEM>>>(Ap, Wb1p, b1p, nullptr, nullptr,
                                           1152, 1152, 1024);

    unsigned* rprev = rmp;
    unsigned* rnext = rmp + M_;

    for (int n = 1; n < T_; n <<= 1) {
        sc_k<<<(M_ * 16) / 256, 256>>>(freq_b, n, rprev, rnext);
        if (n < 1024) {
            gemm_tc<MODE_LOOP>
                <<<dim3(9, M_ / 128), 256, SMEM>>>(SCp, Wb2p, b2p, nullptr, rnext,
                                                   1152, 1152, 128);
        } else {
            gemm_tc<MODE_SCAN>
                <<<dim3(8, M_ / 128), 256, SMEM>>>(SCp, Wb2p, b2p, nullptr, rnext,
                                                   1024, 1152, 128);
        }
        unsigned* tmp = rprev; rprev = rnext; rnext = tmp;
    }

    // out = (q*v*s) @ proj_W + proj_b
    aproj_k<<<(M_ * C_) / 1024, 256>>>(rprev);
    gemm_tc<MODE_PROJ>
        <<<dim3(8, M_ / 128), 256, SMEM>>>(Ap, pWp, proj_b, out, nullptr,
                                           1024, 1024, 1024);
}

// round 17
// speedup vs baseline: 1.0209x; 1.0209x over previous
#include <cuda_runtime.h>
#include <math.h>
#include <stdint.h>

#define B_  8
#define T_  2048
#define C_  1024
#define NF_ 64
#define M_  (B_*T_)      /* 16384 */
#define TNF 128

// ---------------- scratch (device globals) ----------------
__device__ float    g_q[(size_t)M_ * C_];      // final q only (tf32)
__device__ float    g_v[(size_t)M_ * C_];      // fp32
__device__ float    g_A[(size_t)M_ * C_];      // x_tf32, later (q*v*s)_tf32
__device__ float    g_G[(size_t)M_ * TNF];     // fp32, loop state
__device__ float    g_SC[(size_t)M_ * TNF];    // tf32
__device__ float    g_Wcat[C_ * TNF];          // fp32 exact [Wtop|Wbot]
__device__ float    g_Wb1[C_ * 1152];          // tf32 [attn_W_v | Wq@Wcat]
__device__ float    g_Wb2[TNF * 1152];         // tf32 [out_W | out_W@Wcat]
__device__ float    g_projW[C_ * C_];          // tf32
__device__ float    g_bias1[1152];             // [attn_b_v | attn_b_q@Wcat]
__device__ float    g_bias2[1152];             // [out_b | out_b@Wcat]
__device__ float    g_idG[NF_];
__device__ unsigned g_rm[2][M_];

enum { MODE_SPLIT = 0, MODE_LOOP = 1, MODE_SCAN = 2, MODE_PROJ = 3 };

__device__ __forceinline__ uint32_t f2tf(float f) {
    uint32_t u; asm("cvt.rna.tf32.f32 %0, %1;" : "=r"(u) : "f"(f)); return u;
}
__device__ __forceinline__ float f2tff(float f) { return __uint_as_float(f2tf(f)); }
__device__ __forceinline__ void mma8(float* c, const uint32_t* a, const uint32_t* b) {
    asm volatile(
        "mma.sync.aligned.m16n8k8.row.col.f32.tf32.tf32.f32 "
        "{%0,%1,%2,%3},{%4,%5,%6,%7},{%8,%9},{%0,%1,%2,%3};\n"
        : "+f"(c[0]), "+f"(c[1]), "+f"(c[2]), "+f"(c[3])
        : "r"(a[0]), "r"(a[1]), "r"(a[2]), "r"(a[3]), "r"(b[0]), "r"(b[1]));
}
__device__ __forceinline__ void cpa16(uint32_t dst, const void* src) {
    asm volatile("cp.async.cg.shared.global [%0], [%1], 16;\n" :: "r"(dst), "l"(src));
}

// ---------------- pipelined tf32 tensor-core GEMM (BM=128, BN=128, BK=32) ----------------
template<int MODE>
__global__ __launch_bounds__(256, 2)
void gemm_tc(const float* __restrict__ A, const float* __restrict__ Bm,
             const float* __restrict__ bias, float* __restrict__ Cmat,
             unsigned* __restrict__ rmw, int N, int ldb, int K)
{
    constexpr int BM = 128, WM = 32, WN = 64, BK = 32;
    constexpr int WARPS_N = 2;
    constexpr int MT = WM / 16, NT = WN / 8;
    constexpr int ASZ = BM * 36;
    constexpr int BSZ = BK * 128;

    extern __shared__ float sm[];
    const uint32_t smbase = (uint32_t)__cvta_generic_to_shared(sm);

    const int tid  = threadIdx.x;
    const int bm   = blockIdx.y * BM;
    const int bn   = blockIdx.x * 128;
    const int warp = tid >> 5, lane = tid & 31;
    const int grp  = lane >> 2, tig = lane & 3;
    const int wm   = warp / WARPS_N, wn = warp % WARPS_N;

    float acc[MT][NT][4];
#pragma unroll
    for (int i = 0; i < MT; i++)
#pragma unroll
        for (int j = 0; j < NT; j++)
#pragma unroll
            for (int r = 0; r < 4; r++) acc[i][j][r] = 0.f;

    const int lr = tid >> 3, lc = (tid & 7) * 4;
    const int kr = tid >> 5;
    const int kchunk = tid & 31;
    const int kphys  = (kchunk ^ ((kr & 3) << 1)) * 4;

    auto ldA = [&](int st, int k0) {
#pragma unroll
        for (int i = 0; i < BM / 32; i++) {
            uint32_t d = smbase + (uint32_t)(st * ASZ + (lr + 32 * i) * 36 + lc) * 4u;
            cpa16(d, &A[(size_t)(bm + lr + 32 * i) * K + k0 + lc]);
        }
    };
    auto ldB = [&](int st, int k0) {
#pragma unroll
        for (int i = 0; i < 4; i++) {
            uint32_t d = smbase + (uint32_t)(2 * ASZ + st * BSZ + (kr + 8 * i) * 128 + kphys) * 4u;
            cpa16(d, &Bm[(size_t)(k0 + kr + 8 * i) * ldb + bn + kchunk * 4]);
        }
    };

    ldA(0, 0); ldB(0, 0);
    asm volatile("cp.async.commit_group;\n");

    const int nk = K / BK;
    for (int it = 0; it < nk; it++) {
        const int st = it & 1;
        if (it + 1 < nk) {
            ldA(st ^ 1, (it + 1) * BK);
            ldB(st ^ 1, (it + 1) * BK);
            asm volatile("cp.async.commit_group;\n");
            asm volatile("cp.async.wait_group 1;\n");
        } else {
            asm volatile("cp.async.wait_group 0;\n");
        }
        __syncthreads();

        const uint32_t* As32 = (const uint32_t*)sm + st * ASZ;
        const uint32_t* Bs32 = (const uint32_t*)sm + 2 * ASZ + st * BSZ;

#pragma unroll
        for (int ks = 0; ks < 4; ks++) {
            const int kk = ks * 8;
            uint32_t af[MT][4], bf[NT][2];
#pragma unroll
            for (int mt = 0; mt < MT; mt++) {
                int r = wm * WM + mt * 16 + grp;
                af[mt][0] = As32[r * 36 + kk + tig];
                af[mt][1] = As32[(r + 8) * 36 + kk + tig];
                af[mt][2] = As32[r * 36 + kk + tig + 4];
                af[mt][3] = As32[(r + 8) * 36 + kk + tig + 4];
            }
#pragma unroll
            for (int nt = 0; nt < NT; nt++) {
                int c = wn * WN + nt * 8 + grp;
                int p = (((c >> 2) ^ (tig << 1)) << 2) | (c & 3);
                bf[nt][0] = Bs32[(kk + tig) * 128 + p];
                bf[nt][1] = Bs32[(kk + tig + 4) * 128 + p];
            }
#pragma unroll
            for (int mt = 0; mt < MT; mt++)
#pragma unroll
                for (int nt = 0; nt < NT; nt++)
                    mma8(acc[mt][nt], af[mt], bf[nt]);
        }
        __syncthreads();
    }

    // ---------------- epilogue ----------------
#pragma unroll
    for (int mt = 0; mt < MT; mt++) {
        int row0 = bm + wm * WM + mt * 16 + grp;
        float mx0 = 0.f, mx1 = 0.f;
#pragma unroll
        for (int nt = 0; nt < NT; nt++) {
            int col = bn + wn * WN + nt * 8 + tig * 2;
            float b0 = bias[col], b1 = bias[col + 1];
            float v0 = acc[mt][nt][0] + b0, v1 = acc[mt][nt][1] + b1;
            float v2 = acc[mt][nt][2] + b0, v3 = acc[mt][nt][3] + b1;
            if (MODE == MODE_SPLIT) {
                if (col < C_) {
                    *(float2*)&g_v[(size_t)row0 * C_ + col]       = make_float2(v0, v1);
                    *(float2*)&g_v[(size_t)(row0 + 8) * C_ + col] = make_float2(v2, v3);
                } else {
                    int lcol = col - C_;
                    *(float2*)&g_G[(size_t)row0 * TNF + lcol]       = make_float2(v0, v1);
                    *(float2*)&g_G[(size_t)(row0 + 8) * TNF + lcol] = make_float2(v2, v3);
                }
            } else if (MODE == MODE_LOOP) {
                if (col < C_) {
                    mx0 = fmaxf(mx0, fmaxf(fabsf(v0), fabsf(v1)));
                    mx1 = fmaxf(mx1, fmaxf(fabsf(v2), fabsf(v3)));
                } else {
                    int lcol = col - C_;
                    *(float2*)&g_G[(size_t)row0 * TNF + lcol]       = make_float2(v0, v1);
                    *(float2*)&g_G[(size_t)(row0 + 8) * TNF + lcol] = make_float2(v2, v3);
                }
            } else if (MODE == MODE_SCAN) {
                mx0 = fmaxf(mx0, fmaxf(fabsf(v0), fabsf(v1)));
                mx1 = fmaxf(mx1, fmaxf(fabsf(v2), fabsf(v3)));
                *(float2*)&g_q[(size_t)row0 * C_ + col]       = make_float2(f2tff(v0), f2tff(v1));
                *(float2*)&g_q[(size_t)(row0 + 8) * C_ + col] = make_float2(f2tff(v2), f2tff(v3));
            } else {
                *(float2*)&Cmat[(size_t)row0 * N + col]       = make_float2(v0, v1);
                *(float2*)&Cmat[(size_t)(row0 + 8) * N + col] = make_float2(v2, v3);
            }
        }
        if (MODE == MODE_SCAN || (MODE == MODE_LOOP && bn < C_)) {
#pragma unroll
            for (int off = 1; off < 4; off <<= 1) {
                mx0 = fmaxf(mx0, __shfl_xor_sync(0xffffffffu, mx0, off));
                mx1 = fmaxf(mx1, __shfl_xor_sync(0xffffffffu, mx1, off));
            }
            if (tig == 0) {
                atomicMax(&rmw[row0],     __float_as_uint(mx0));
                atomicMax(&rmw[row0 + 8], __float_as_uint(mx1));
            }
        }
    }
}

// ---------------- pre-pass kernels ----------------
__global__ void cvt_k(const float* __restrict__ src, float* __restrict__ dst)
{
    size_t i = ((size_t)blockIdx.x * 256 + threadIdx.x) * 4;
    float4 v = *(const float4*)&src[i];
    v.x = f2tff(v.x); v.y = f2tff(v.y); v.z = f2tff(v.z); v.w = f2tff(v.w);
    *(float4*)&dst[i] = v;
}

__global__ void pack_wcat_k(const float* __restrict__ freqW)
{
    int idx = blockIdx.x * 256 + threadIdx.x;      // < 1024*128
    int k = idx >> 7, j = idx & 127;
    g_Wcat[idx] = (j < 64) ? freqW[k * 64 + j] : freqW[(k + 1024) * 64 + (j - 64)];
}

__global__ void wb1_k(const float* __restrict__ attnW)
{
    int i = blockIdx.y * 2 + (threadIdx.x >> 7);
    int c = blockIdx.x * 128 + (threadIdx.x & 127);
    float w;
    if (c < C_) {
        w = attnW[(size_t)i * 2048 + C_ + c];               // v-columns
    } else {
        int j = c - C_;                                     // W1 = Wq @ Wcat
        float s = 0.f;
        for (int k = 0; k < C_; k++)
            s = fmaf(attnW[(size_t)i * 2048 + k], g_Wcat[k * TNF + j], s);
        w = s;
    }
    g_Wb1[i * 1152 + c] = f2tff(w);
}

__global__ void wb2_k(const float* __restrict__ outW)
{
    int i = blockIdx.y * 2 + (threadIdx.x >> 7);
    int c = blockIdx.x * 128 + (threadIdx.x & 127);
    float w;
    if (c < C_) {
        w = outW[(size_t)i * C_ + c];
    } else {
        int j = c - C_;                                     // W2 = out_W @ Wcat
        float s = 0.f;
        for (int k = 0; k < C_; k++)
            s = fmaf(outW[(size_t)i * C_ + k], g_Wcat[k * TNF + j], s);
        w = s;
    }
    g_Wb2[i * 1152 + c] = f2tff(w);
}

__global__ void bias1_k(const float* __restrict__ attn_b)
{
    int c = blockIdx.x * 256 + threadIdx.x;
    if (c >= 1152) return;
    if (c < C_) { g_bias1[c] = attn_b[C_ + c]; return; }
    int j = c - C_;
    float s = 0.f;
    for (int k = 0; k < C_; k++) s = fmaf(attn_b[k], g_Wcat[k * TNF + j], s);
    g_bias1[c] = s;
}

__global__ void bias2_k(const float* __restrict__ out_b)
{
    int c = blockIdx.x * 256 + threadIdx.x;
    if (c >= 1152) return;
    if (c < C_) { g_bias2[c] = out_b[c]; return; }
    int j = c - C_;
    float s = 0.f;
    for (int k = 0; k < C_; k++) s = fmaf(out_b[k], g_Wcat[k * TNF + j], s);
    g_bias2[c] = s;
}

__global__ void idg_k(const float* __restrict__ freqW, const float* __restrict__ identity)
{
    int j = threadIdx.x;   // 64
    float s = 0.f;
    for (int k = 0; k < C_; k++) s = fmaf(identity[k], freqW[k * 64 + j], s);
    g_idG[j] = s;
}

__global__ void init_rm_k()
{
    g_rm[0][blockIdx.x * 256 + threadIdx.x] = __float_as_uint(1.0f - 1e-6f);
}

// shift + scale + sincos -> g_SC (tf32); zero rmnext. 4 j's per thread.
__global__ __launch_bounds__(256)
void sc_k(const float* __restrict__ freq_b, int n,
          const unsigned* __restrict__ rmprev, unsigned* __restrict__ rmnext)
{
    int idx = blockIdx.x * 256 + threadIdx.x;      // < M*16
    int row = idx >> 4, jq = (idx & 15) * 4;
    if (jq == 0) rmnext[row] = 0u;
    int t = row & (T_ - 1);
    float sown = 1.f / (__uint_as_float(rmprev[row]) + 1e-6f);
    float4 g2 = *(const float4*)&g_G[(size_t)row * TNF + 64 + jq];
    float4 g1;
    if (t >= n) {
        float sp = 1.f / (__uint_as_float(rmprev[row - n]) + 1e-6f);
        g1 = *(const float4*)&g_G[(size_t)(row - n) * TNF + jq];
        g1.x *= sp; g1.y *= sp; g1.z *= sp; g1.w *= sp;
    } else {
        g1 = *(const float4*)&g_idG[jq];
    }
    float4 fb = *(const float4*)&freq_b[jq];
    float f0 = g1.x + g2.x * sown + fb.x;
    float f1 = g1.y + g2.y * sown + fb.y;
    float f2 = g1.z + g2.z * sown + fb.z;
    float f3 = g1.w + g2.w * sown + fb.w;
    float s0, c0, s1, c1, s2, c2, s3, c3;
    sincosf(f0, &s0, &c0); sincosf(f1, &s1, &c1);
    sincosf(f2, &s2, &c2); sincosf(f3, &s3, &c3);
    *(float4*)&g_SC[(size_t)row * TNF + jq] =
        make_float4(f2tff(s0), f2tff(s1), f2tff(s2), f2tff(s3));
    *(float4*)&g_SC[(size_t)row * TNF + 64 + jq] =
        make_float4(f2tff(c0), f2tff(c1), f2tff(c2), f2tff(c3));
}

// A_proj = tf32(q * v * s)
__global__ __launch_bounds__(256)
void aproj_k(const unsigned* __restrict__ rm)
{
    size_t i = ((size_t)blockIdx.x * 256 + threadIdx.x) * 4;
    int row = (int)(i >> 10);
    float s = 1.f / (__uint_as_float(rm[row]) + 1e-6f);
    float4 q = *(const float4*)&g_q[i];
    float4 v = *(const float4*)&g_v[i];
    q.x = f2tff(q.x * v.x * s); q.y = f2tff(q.y * v.y * s);
    q.z = f2tff(q.z * v.z * s); q.w = f2tff(q.w * v.w * s);
    *(float4*)&g_A[i] = q;
}

// ---------------- launch ----------------
extern "C" void kernel_launch(void* const* d_in, const int* in_sizes, int n_in,
                              void* d_out, int out_size)
{
    (void)in_sizes; (void)n_in; (void)out_size;
    const float* x        = (const float*)d_in[0];
    const float* attn_W   = (const float*)d_in[1];
    const float* attn_b   = (const float*)d_in[2];
    const float* freq_W   = (const float*)d_in[3];
    const float* freq_b   = (const float*)d_in[4];
    const float* out_W    = (const float*)d_in[5];
    const float* out_b    = (const float*)d_in[6];
    const float* proj_W   = (const float*)d_in[7];
    const float* proj_b   = (const float*)d_in[8];
    const float* identity = (const float*)d_in[9];
    float* out = (float*)d_out;

    float *Ap, *SCp, *Wb1p, *Wb2p, *pWp, *b1p, *b2p;
    unsigned* rmp;
    cudaGetSymbolAddress((void**)&Ap,   g_A);
    cudaGetSymbolAddress((void**)&SCp,  g_SC);
    cudaGetSymbolAddress((void**)&Wb1p, g_Wb1);
    cudaGetSymbolAddress((void**)&Wb2p, g_Wb2);
    cudaGetSymbolAddress((void**)&pWp,  g_projW);
    cudaGetSymbolAddress((void**)&b1p,  g_bias1);
    cudaGetSymbolAddress((void**)&b2p,  g_bias2);
    cudaGetSymbolAddress((void**)&rmp,  g_rm);

    constexpr int SMEM = 2 * (128 * 36 + 32 * 128) * 4;   // 69632
    cudaFuncSetAttribute(gemm_tc<MODE_SPLIT>, cudaFuncAttributeMaxDynamicSharedMemorySize, SMEM);
    cudaFuncSetAttribute(gemm_tc<MODE_LOOP>,  cudaFuncAttributeMaxDynamicSharedMemorySize, SMEM);
    cudaFuncSetAttribute(gemm_tc<MODE_SCAN>,  cudaFuncAttributeMaxDynamicSharedMemorySize, SMEM);
    cudaFuncSetAttribute(gemm_tc<MODE_PROJ>,  cudaFuncAttributeMaxDynamicSharedMemorySize, SMEM);

    // pre-pass
    pack_wcat_k<<<512, 256>>>(freq_W);
    cvt_k<<<(M_ * C_) / 1024, 256>>>(x, Ap);
    cvt_k<<<(C_ * C_) / 1024, 256>>>(proj_W, pWp);
    wb1_k<<<dim3(9, 512), 256>>>(attn_W);
    wb2_k<<<dim3(9, 64), 256>>>(out_W);
    bias1_k<<<5, 256>>>(attn_b);
    bias2_k<<<5, 256>>>(out_b);
    idg_k<<<1, 64>>>(freq_W, identity);
    init_rm_k<<<M_ / 256, 256>>>();

    // split: [v | G0] = x @ [Wv | Wq@Wcat] + bias1
    gemm_tc<MODE_SPLIT>
        <<<dim3(9, M_ / 128), 256, SMEM>>>(Ap, Wb1p, b1p, nullptr, nullptr,
                                           1152, 1152, 1024);

    unsigned* rprev = rmp;
    unsigned* rnext = rmp + M_;

    for (int n = 1; n < T_; n <<= 1) {
        sc_k<<<(M_ * 16) / 256, 256>>>(freq_b, n, rprev, rnext);
        if (n < 1024) {
            gemm_tc<MODE_LOOP>
                <<<dim3(9, M_ / 128), 256, SMEM>>>(SCp, Wb2p, b2p, nullptr, rnext,
                                                   1152, 1152, 128);
        } else {
            gemm_tc<MODE_SCAN>
                <<<dim3(8, M_ / 128), 256, SMEM>>>(SCp, Wb2p, b2p, nullptr, rnext,
                                                   1024, 1152, 128);
        }
        unsigned* tmp = rprev; rprev = rnext; rnext = tmp;
    }

    // out = (q*v*s) @ proj_W + proj_b
    aproj_k<<<(M_ * C_) / 1024, 256>>>(rprev);
    gemm_tc<MODE_PROJ>
        <<<dim3(8, M_ / 128), 256, SMEM>>>(Ap, pWp, proj_b, out, nullptr,
                                           1024, 1024, 1024);
}